// round 4
// baseline (speedup 1.0000x reference)
#include <cuda_runtime.h>

#define ALPHA 0.01f

// Scratch (static device globals — allocation-free per harness rules)
__device__ float g_h1[32u*64u*112u*112u];   // 102.8 MB: conv1 pooled output [32,64,112,112]
__device__ float g_h2[32u*64u*56u*56u];     //  25.7 MB: conv2 pooled output [32,64,56,56]
__device__ float g_fcp[196*32*10];          // FC split-K partials

// ---- packed f32x2 helpers (sm_100a; ptxas won't auto-fuse, must use PTX) ----
__device__ __forceinline__ unsigned long long pack2(float x, float y) {
    unsigned long long r;
    asm("mov.b64 %0, {%1, %2};" : "=l"(r) : "f"(x), "f"(y));
    return r;
}
__device__ __forceinline__ unsigned long long ffma2(unsigned long long a,
                                                    unsigned long long b,
                                                    unsigned long long c) {
    unsigned long long d;
    asm("fma.rn.f32x2 %0, %1, %2, %3;" : "=l"(d) : "l"(a), "l"(b), "l"(c));
    return d;
}
__device__ __forceinline__ void unpack2(unsigned long long v, float& x, float& y) {
    asm("mov.b64 {%0, %1}, %2;" : "=f"(x), "=f"(y) : "l"(v));
}
__device__ __forceinline__ float leaky(float v) { return v > 0.f ? v : ALPHA * v; }

// ---------------------------------------------------------------------------
// Kernel 1: conv1(3->64, 3x3, pad1) + leaky + maxpool2, f32x2-packed over oc pairs
// Grid: (49 tiles, 32 batch), 256 threads. Thread: 1 pooled pixel, 64 oc.
// ---------------------------------------------------------------------------
__global__ __launch_bounds__(256) void conv1_kernel(const float* __restrict__ x,
                                                    const float* __restrict__ w1,
                                                    const float* __restrict__ b1)
{
    __shared__ float s_in[3][34][34];                    // input tile (+1 halo)
    __shared__ __align__(16) float s_w2[27][64];         // transposed: [tap][oc]
    __shared__ float s_b[64];

    const int tid  = threadIdx.x;
    const int t    = blockIdx.x;          // 0..48
    const int b    = blockIdx.y;          // 0..31
    const int tpy0 = (t / 7) * 16;
    const int tpx0 = (t % 7) * 16;
    const int cy0  = tpy0 * 2, cx0 = tpx0 * 2;

    for (int i = tid; i < 3*34*34; i += 256) {
        int c  = i / (34*34); int r = i % (34*34);
        int yy = r / 34, xx = r % 34;
        int gy = cy0 - 1 + yy, gx = cx0 - 1 + xx;
        float v = 0.f;
        if (gy >= 0 && gy < 224 && gx >= 0 && gx < 224)
            v = x[((b*3 + c)*224 + gy)*224 + gx];
        s_in[c][yy][xx] = v;
    }
    for (int i = tid; i < 1728; i += 256) {
        int oc = i / 27, tap = i % 27;
        s_w2[tap][oc] = w1[i];
    }
    if (tid < 64) s_b[tid] = b1[tid];
    __syncthreads();

    const int py = tid >> 4, px = tid & 15;
    const int ly = py * 2,  lx = px * 2;

    // 4x4 patch per channel, replicated into both f32x2 lanes
    unsigned long long p2[3][4][4];
    #pragma unroll
    for (int c = 0; c < 3; c++)
        #pragma unroll
        for (int i = 0; i < 4; i++)
            #pragma unroll
            for (int j = 0; j < 4; j++) {
                float v = s_in[c][ly+i][lx+j];
                p2[c][i][j] = pack2(v, v);
            }

    float* outp = &g_h1[((b*64)*112 + (tpy0+py))*112 + (tpx0+px)];
    for (int oc = 0; oc < 64; oc += 2) {
        unsigned long long bb = pack2(s_b[oc], s_b[oc+1]);
        unsigned long long a00 = bb, a01 = bb, a10 = bb, a11 = bb;
        #pragma unroll
        for (int c = 0; c < 3; c++)
            #pragma unroll
            for (int ky = 0; ky < 3; ky++)
                #pragma unroll
                for (int kx = 0; kx < 3; kx++) {
                    int tap = c*9 + ky*3 + kx;
                    // oc-pair of weights, contiguous; warp-uniform -> LDS broadcast
                    unsigned long long w = *(const unsigned long long*)&s_w2[tap][oc];
                    a00 = ffma2(p2[c][ky  ][kx  ], w, a00);
                    a01 = ffma2(p2[c][ky  ][kx+1], w, a01);
                    a10 = ffma2(p2[c][ky+1][kx  ], w, a10);
                    a11 = ffma2(p2[c][ky+1][kx+1], w, a11);
                }
        float v00a, v00b, v01a, v01b, v10a, v10b, v11a, v11b;
        unpack2(a00, v00a, v00b); unpack2(a01, v01a, v01b);
        unpack2(a10, v10a, v10b); unpack2(a11, v11a, v11b);
        // leaky is monotonic: leaky(max) == max(leaky)
        float m0 = fmaxf(fmaxf(v00a, v01a), fmaxf(v10a, v11a));
        float m1 = fmaxf(fmaxf(v00b, v01b), fmaxf(v10b, v11b));
        outp[oc*112*112]     = leaky(m0);
        outp[(oc+1)*112*112] = leaky(m1);
    }
}

// ---------------------------------------------------------------------------
// Kernel 2: conv2(64->64, 3x3, pad1) + leaky + maxpool2  (dominant kernel)
// Grid: (49 tiles, 32 batch), 256 threads.
// Thread: 2x2 conv pixels x 16 oc = 32 f32x2 accumulators (oc-pair packed).
// Input tile stored in smem PRE-DUPLICATED ({v,v} pairs) so the hot loop loads
// lane-replicated f32x2 operands with plain LDS.64 — zero packing movs.
// No forced min-blocks: let ptxas use ~124 regs without spilling (2 CTAs still fit).
// ---------------------------------------------------------------------------
__global__ __launch_bounds__(256) void conv2_kernel(const float* __restrict__ w2,
                                                    const float* __restrict__ b2)
{
    __shared__ __align__(16) float s_in2[8][18][36];  // 20.7 KB, duplicated pairs
    __shared__ __align__(16) float s_w[8][9][64];     // 18.4 KB, [ic][tap][oc]

    const int tid  = threadIdx.x;
    const int t    = blockIdx.x;          // 0..48
    const int b    = blockIdx.y;
    const int tpy0 = (t / 7) * 8;
    const int tpx0 = (t % 7) * 8;
    const int cy0  = tpy0 * 2, cx0 = tpx0 * 2;

    const int ocg = tid & 3, oc0 = ocg * 16;
    const int pix = tid >> 2;
    const int ppy = pix >> 3, ppx = pix & 7;
    const int ly  = ppy * 2, lx = ppx * 2;

    unsigned long long acc2[2][2][8];
    #pragma unroll
    for (int j = 0; j < 8; j++) {
        unsigned long long bb = pack2(b2[oc0 + 2*j], b2[oc0 + 2*j + 1]);
        acc2[0][0][j] = bb; acc2[0][1][j] = bb; acc2[1][0][j] = bb; acc2[1][1][j] = bb;
    }

    for (int ic0 = 0; ic0 < 64; ic0 += 8) {
        for (int i = tid; i < 8*18*18; i += 256) {
            int ic = i / 324; int r = i % 324;
            int yy = r / 18, xx = r % 18;
            int gy = cy0 - 1 + yy, gx = cx0 - 1 + xx;
            float v = 0.f;
            if (gy >= 0 && gy < 112 && gx >= 0 && gx < 112)
                v = g_h1[((b*64 + ic0 + ic)*112 + gy)*112 + gx];
            *(unsigned long long*)&s_in2[ic][yy][2*xx] = pack2(v, v);
        }
        for (int i = tid; i < 8*9*64; i += 256) {
            int ic = i / 576; int r = i % 576;
            int tap = r / 64, oc = r % 64;
            s_w[ic][tap][oc] = w2[(oc*64 + ic0 + ic)*9 + tap];
        }
        __syncthreads();

        #pragma unroll
        for (int ic = 0; ic < 8; ic++) {
            // 4x4 patch, already lane-duplicated in smem: 16 x LDS.64
            unsigned long long p2[4][4];
            #pragma unroll
            for (int iy = 0; iy < 4; iy++)
                #pragma unroll
                for (int ix = 0; ix < 4; ix++)
                    p2[iy][ix] = *(const unsigned long long*)&s_in2[ic][ly+iy][2*(lx+ix)];

            #pragma unroll
            for (int ky = 0; ky < 3; ky++)
                #pragma unroll
                for (int kx = 0; kx < 3; kx++) {
                    // 16 oc = 8 f32x2 weight pairs via 4 x LDS.128
                    const ulonglong2* wp =
                        (const ulonglong2*)&s_w[ic][ky*3 + kx][oc0];
                    ulonglong2 wA = wp[0], wB = wp[1], wC = wp[2], wD = wp[3];
                    unsigned long long w[8] = { wA.x, wA.y, wB.x, wB.y,
                                                wC.x, wC.y, wD.x, wD.y };
                    #pragma unroll
                    for (int dy = 0; dy < 2; dy++)
                        #pragma unroll
                        for (int dx = 0; dx < 2; dx++) {
                            unsigned long long inv = p2[ky+dy][kx+dx];
                            #pragma unroll
                            for (int j = 0; j < 8; j++)
                                acc2[dy][dx][j] = ffma2(w[j], inv, acc2[dy][dx][j]);
                        }
                }
        }
        __syncthreads();
    }

    const int oy = tpy0 + ppy, ox = tpx0 + ppx;
    #pragma unroll
    for (int j = 0; j < 8; j++) {
        float e00, o00, e01, o01, e10, o10, e11, o11;
        unpack2(acc2[0][0][j], e00, o00); unpack2(acc2[0][1][j], e01, o01);
        unpack2(acc2[1][0][j], e10, o10); unpack2(acc2[1][1][j], e11, o11);
        float me = fmaxf(fmaxf(e00, e01), fmaxf(e10, e11));
        float mo = fmaxf(fmaxf(o00, o01), fmaxf(o10, o11));
        g_h2[((b*64 + oc0 + 2*j  )*56 + oy)*56 + ox] = leaky(me);
        g_h2[((b*64 + oc0 + 2*j+1)*56 + oy)*56 + ox] = leaky(mo);
    }
}

// ---------------------------------------------------------------------------
// Kernel 3: FC split-K partials. Grid 196 blocks x 256 threads.
// wfc chunk transposed in smem to [c][k] so per-c loads are conflict-free LDS.128.
// ---------------------------------------------------------------------------
__global__ __launch_bounds__(256) void fc_partial_kernel(const float* __restrict__ wfc)
{
    __shared__ __align__(16) float s_wt[10][1024];   // 40 KB
    const int tid = threadIdx.x;
    const int k0  = blockIdx.x * 1024;

    for (int i = tid; i < 10240; i += 256) {
        int k = i / 10, c = i % 10;        // coalesced global read, scattered smem write
        s_wt[c][k] = wfc[k0*10 + i];
    }
    __syncthreads();

    const int warp = tid >> 5, lane = tid & 31;
    for (int bg = 0; bg < 4; bg++) {
        int b = bg*8 + warp;
        float acc[10];
        #pragma unroll
        for (int c = 0; c < 10; c++) acc[c] = 0.f;

        const float4* hb = (const float4*)&g_h2[b*200704 + k0];
        for (int k4 = lane; k4 < 256; k4 += 32) {
            float4 hv = hb[k4];
            #pragma unroll
            for (int c = 0; c < 10; c++) {
                float4 wv = *(const float4*)&s_wt[c][k4*4];   // lane-contiguous LDS.128
                acc[c] += hv.x*wv.x + hv.y*wv.y + hv.z*wv.z + hv.w*wv.w;
            }
        }
        #pragma unroll
        for (int c = 0; c < 10; c++) {
            #pragma unroll
            for (int off = 16; off; off >>= 1)
                acc[c] += __shfl_xor_sync(0xffffffffu, acc[c], off);
        }
        if (lane == 0) {
            #pragma unroll
            for (int c = 0; c < 10; c++)
                g_fcp[(blockIdx.x*32 + b)*10 + c] = acc[c];
        }
    }
}

// ---------------------------------------------------------------------------
// Kernel 4: final reduction. Grid 32 (per batch), 224 threads (7 full warps).
// Deterministic: fixed per-warp shfl order + fixed 7-term smem sum.
// ---------------------------------------------------------------------------
__global__ __launch_bounds__(224) void fc_reduce_kernel(const float* __restrict__ bfc,
                                                        float* __restrict__ out)
{
    __shared__ float s_part[7][10];
    const int tid = threadIdx.x;
    const int b   = blockIdx.x;
    const int warp = tid >> 5, lane = tid & 31;

    float a[10];
    #pragma unroll
    for (int c = 0; c < 10; c++) a[c] = 0.f;

    if (tid < 196) {
        const float2* p = (const float2*)&g_fcp[(tid*32 + b)*10];   // 8B-aligned
        #pragma unroll
        for (int h = 0; h < 5; h++) {
            float2 v = p[h];
            a[2*h]   = v.x;
            a[2*h+1] = v.y;
        }
    }
    #pragma unroll
    for (int c = 0; c < 10; c++) {
        #pragma unroll
        for (int off = 16; off; off >>= 1)
            a[c] += __shfl_xor_sync(0xffffffffu, a[c], off);
    }
    if (lane == 0)
        #pragma unroll
        for (int c = 0; c < 10; c++) s_part[warp][c] = a[c];
    __syncthreads();

    if (tid < 10) {
        float s = bfc[tid];
        #pragma unroll
        for (int w = 0; w < 7; w++) s += s_part[w][tid];
        out[b*10 + tid] = s;
    }
}

// ---------------------------------------------------------------------------
extern "C" void kernel_launch(void* const* d_in, const int* in_sizes, int n_in,
                              void* d_out, int out_size)
{
    const float* x   = (const float*)d_in[0];
    const float* w1  = (const float*)d_in[1];
    const float* b1  = (const float*)d_in[2];
    const float* w2  = (const float*)d_in[3];
    const float* b2  = (const float*)d_in[4];
    const float* wfc = (const float*)d_in[5];
    const float* bfc = (const float*)d_in[6];
    float* out = (float*)d_out;

    conv1_kernel<<<dim3(49, 32), 256>>>(x, w1, b1);
    conv2_kernel<<<dim3(49, 32), 256>>>(w2, b2);
    fc_partial_kernel<<<196, 256>>>(wfc);
    fc_reduce_kernel<<<32, 224>>>(bfc, out);
}

// round 11
// speedup vs baseline: 1.9862x; 1.9862x over previous
#include <cuda_runtime.h>
#include <cuda_bf16.h>
#include <cstdint>

#define ALPHA 0.01f

// ---------------------------------------------------------------------------
// Scratch (static device globals — allocation-free per harness rules)
// ---------------------------------------------------------------------------
__device__ float g_h1[32u*64u*112u*112u];        // 102.8 MB conv1 pooled out (fp32)
__device__ float g_h2[32u*64u*56u*56u];          //  25.7 MB conv2 pooled out
__device__ float g_fcp[196*32*10];               // FC split-K partials
__device__ unsigned long long g_w2t_hi[9*1024];  // w2 [tap][oc][ic] bf16 hi (16 ULL/oc)
__device__ unsigned long long g_w2t_lo[9*1024];  // ... bf16 lo

__device__ __forceinline__ uint32_t smem_to_u32(const void* p) {
    uint32_t a;
    asm("{ .reg .u64 t; cvta.to.shared.u64 t, %1; cvt.u32.u64 %0, t; }" : "=r"(a) : "l"(p));
    return a;
}
__device__ __forceinline__ void ldsm_x4(uint32_t* r, uint32_t addr) {
    asm volatile("ldmatrix.sync.aligned.m8n8.x4.shared.b16 {%0,%1,%2,%3}, [%4];"
                 : "=r"(r[0]), "=r"(r[1]), "=r"(r[2]), "=r"(r[3]) : "r"(addr));
}
__device__ __forceinline__ void mma_bf16(float* d, const uint32_t* a,
                                         uint32_t b0, uint32_t b1) {
    asm volatile("mma.sync.aligned.m16n8k16.row.col.f32.bf16.bf16.f32 "
                 "{%0,%1,%2,%3}, {%4,%5,%6,%7}, {%8,%9}, {%0,%1,%2,%3};"
                 : "+f"(d[0]), "+f"(d[1]), "+f"(d[2]), "+f"(d[3])
                 : "r"(a[0]), "r"(a[1]), "r"(a[2]), "r"(a[3]), "r"(b0), "r"(b1));
}
// ---- packed f32x2 helpers (conv1, proven in R3/R4) ----
__device__ __forceinline__ unsigned long long pack2(float x, float y) {
    unsigned long long r;
    asm("mov.b64 %0, {%1, %2};" : "=l"(r) : "f"(x), "f"(y));
    return r;
}
__device__ __forceinline__ unsigned long long ffma2(unsigned long long a,
                                                    unsigned long long b,
                                                    unsigned long long c) {
    unsigned long long d;
    asm("fma.rn.f32x2 %0, %1, %2, %3;" : "=l"(d) : "l"(a), "l"(b), "l"(c));
    return d;
}
__device__ __forceinline__ void unpack2(unsigned long long v, float& x, float& y) {
    asm("mov.b64 {%0, %1}, %2;" : "=f"(x), "=f"(y) : "l"(v));
}
__device__ __forceinline__ float leaky(float v) { return v > 0.f ? v : ALPHA * v; }

// ---------------------------------------------------------------------------
// Kernel 0: transpose+split w2 -> g_w2t_{hi,lo}[tap][oc][ic] bf16 (one-off)
// bf16-linear index i = tap*4096 + oc*64 + ic  ==  ULL index tap*1024+oc*16+ic/4
// ---------------------------------------------------------------------------
__global__ void prep_w2_kernel(const float* __restrict__ w2)
{
    int i = blockIdx.x * blockDim.x + threadIdx.x;
    if (i >= 9*64*64) return;
    int tap = i / 4096, r = i % 4096;
    int oc = r / 64, ic = r % 64;
    float v = w2[(oc*64 + ic)*9 + tap];
    __nv_bfloat16 hi = __float2bfloat16(v);
    __nv_bfloat16 lo = __float2bfloat16(v - __bfloat162float(hi));
    ((__nv_bfloat16*)g_w2t_hi)[i] = hi;
    ((__nv_bfloat16*)g_w2t_lo)[i] = lo;
}

// ---------------------------------------------------------------------------
// Kernel 1: conv1(3->64) + leaky + maxpool2, f32x2-packed (R3/R4 proven, fp32 out)
// ---------------------------------------------------------------------------
__global__ __launch_bounds__(256) void conv1_kernel(const float* __restrict__ x,
                                                    const float* __restrict__ w1,
                                                    const float* __restrict__ b1)
{
    __shared__ float s_in[3][34][34];
    __shared__ __align__(16) float s_w2[27][64];
    __shared__ float s_b[64];

    const int tid  = threadIdx.x;
    const int t    = blockIdx.x;          // 0..48
    const int b    = blockIdx.y;
    const int tpy0 = (t / 7) * 16;
    const int tpx0 = (t % 7) * 16;
    const int cy0  = tpy0 * 2, cx0 = tpx0 * 2;

    for (int i = tid; i < 3*34*34; i += 256) {
        int c  = i / (34*34); int r = i % (34*34);
        int yy = r / 34, xx = r % 34;
        int gy = cy0 - 1 + yy, gx = cx0 - 1 + xx;
        float v = 0.f;
        if (gy >= 0 && gy < 224 && gx >= 0 && gx < 224)
            v = x[((b*3 + c)*224 + gy)*224 + gx];
        s_in[c][yy][xx] = v;
    }
    for (int i = tid; i < 1728; i += 256) {
        int oc = i / 27, tap = i % 27;
        s_w2[tap][oc] = w1[i];
    }
    if (tid < 64) s_b[tid] = b1[tid];
    __syncthreads();

    const int py = tid >> 4, px = tid & 15;
    const int ly = py * 2,  lx = px * 2;

    unsigned long long p2[3][4][4];
    #pragma unroll
    for (int c = 0; c < 3; c++)
        #pragma unroll
        for (int i = 0; i < 4; i++)
            #pragma unroll
            for (int j = 0; j < 4; j++) {
                float v = s_in[c][ly+i][lx+j];
                p2[c][i][j] = pack2(v, v);
            }

    float* outp = &g_h1[((b*64)*112 + (tpy0+py))*112 + (tpx0+px)];
    for (int oc = 0; oc < 64; oc += 2) {
        unsigned long long bb = pack2(s_b[oc], s_b[oc+1]);
        unsigned long long a00 = bb, a01 = bb, a10 = bb, a11 = bb;
        #pragma unroll
        for (int c = 0; c < 3; c++)
            #pragma unroll
            for (int ky = 0; ky < 3; ky++)
                #pragma unroll
                for (int kx = 0; kx < 3; kx++) {
                    int tap = c*9 + ky*3 + kx;
                    unsigned long long w = *(const unsigned long long*)&s_w2[tap][oc];
                    a00 = ffma2(p2[c][ky  ][kx  ], w, a00);
                    a01 = ffma2(p2[c][ky  ][kx+1], w, a01);
                    a10 = ffma2(p2[c][ky+1][kx  ], w, a10);
                    a11 = ffma2(p2[c][ky+1][kx+1], w, a11);
                }
        float v00a, v00b, v01a, v01b, v10a, v10b, v11a, v11b;
        unpack2(a00, v00a, v00b); unpack2(a01, v01a, v01b);
        unpack2(a10, v10a, v10b); unpack2(a11, v11a, v11b);
        float m0 = fmaxf(fmaxf(v00a, v01a), fmaxf(v10a, v11a));
        float m1 = fmaxf(fmaxf(v00b, v01b), fmaxf(v10b, v11b));
        outp[oc*112*112]     = leaky(m0);
        outp[(oc+1)*112*112] = leaky(m1);
    }
}

// ---------------------------------------------------------------------------
// Kernel 2: conv2(64->64) + leaky + maxpool2 via mma.sync bf16 (3-pass split).
// Block 256 thr / 8 warps, conv tile 16y x 8x = 128 pixels.
// Warp w: pixels [16w,16w+16) x ALL 64 oc (1 A-frag, 8 n-frags, acc[8][4]).
// Halo split hi/lo on the fly from fp32 g_h1. D staged via smem (overlay on A).
// ---------------------------------------------------------------------------
#define C2_AHI   256
#define C2_ALO   26176                      // 256 + 180*144
#define C2_WHI   52096                      // + 180*144
#define C2_WLO   135040                     // + 9*64*144
#define C2_TOTAL 217984                     // + 9*64*144
#define C2_ALO_D 25920
#define C2_WLO_D 82944

__global__ __launch_bounds__(256) void conv2_kernel(const float* __restrict__ b2)
{
    extern __shared__ __align__(16) char smem[];
    const uint32_t sb = smem_to_u32(smem);
    const int tid  = threadIdx.x;
    const int lane = tid & 31;
    const int wid  = tid >> 5;

    const int t = blockIdx.x;               // 0..97 = 7 (y,16) x 14 (x,8)
    const int b = blockIdx.y;
    const int cy0 = (t / 14) * 16;
    const int cx0 = (t % 14) * 8;

    // 0) defensively zero ALL smem (diagnostic; removed once passing)
    {
        int4 z = {0,0,0,0};
        for (int i = tid; i < C2_TOTAL/16; i += 256) ((int4*)smem)[i] = z;
    }
    __syncthreads();

    float* s_bias = (float*)smem;           // [0,256)
    if (tid < 64) s_bias[tid] = b2[tid];

    // 1) stage weights [tap][oc][ic] hi/lo, row stride 144 B.
    //    16 ULLs per oc row (64 ic), 1024 ULLs per tap.   (R10 FIX)
    for (int i = tid; i < 9*1024; i += 256) {
        int tap = i >> 10, r = i & 1023;
        int oc = r >> 4, icg = r & 15;
        uint32_t doff = (uint32_t)tap*9216u + (uint32_t)oc*144u + (uint32_t)icg*8u;
        *(unsigned long long*)(smem + C2_WHI + doff) = g_w2t_hi[i];
        *(unsigned long long*)(smem + C2_WLO + doff) = g_w2t_lo[i];
    }

    // 2) stage halo 18x10 x 64ic, split fp32 -> bf16 hi/lo on the fly
    {
        __nv_bfloat16* s_ahi = (__nv_bfloat16*)(smem + C2_AHI);
        __nv_bfloat16* s_alo = (__nv_bfloat16*)(smem + C2_ALO);
        for (int i = tid; i < 64*180; i += 256) {
            int ic  = i / 180;
            int pos = i % 180;
            int r = pos / 10, c = pos % 10;
            int gy = cy0 - 1 + r, gx = cx0 - 1 + c;
            float v = 0.f;
            if (gy >= 0 && gy < 112 && gx >= 0 && gx < 112)
                v = g_h1[(((unsigned)(b*64 + ic))*112u + gy)*112u + gx];
            __nv_bfloat16 hi = __float2bfloat16(v);
            __nv_bfloat16 lo = __float2bfloat16(v - __bfloat162float(hi));
            s_ahi[pos*72 + ic] = hi;
            s_alo[pos*72 + ic] = lo;
        }
    }
    __syncthreads();

    // 3) mainloop (no syncs): warp w -> pixels [16w, 16w+16), all 64 oc
    uint32_t aBase;
    {
        int p = wid*16 + (lane & 15);                     // pixel index
        int pos = (p >> 3)*10 + (p & 7);                  // 16x8 tile -> 18x10 halo
        aBase = sb + C2_AHI + (uint32_t)pos*144u + (uint32_t)(lane >> 4)*16u;
    }
    uint32_t bBase[4];
    #pragma unroll
    for (int nb = 0; nb < 4; nb++) {
        int ocrow = nb*16 + (lane & 7) + ((lane >> 4) & 1)*8;
        bBase[nb] = sb + C2_WHI + (uint32_t)ocrow*144u + (uint32_t)((lane >> 3) & 1)*16u;
    }

    float acc[8][4];
    #pragma unroll
    for (int nf = 0; nf < 8; nf++)
        #pragma unroll
        for (int c = 0; c < 4; c++) acc[nf][c] = 0.f;

    #pragma unroll
    for (int tap = 0; tap < 9; tap++) {
        const uint32_t aS = (uint32_t)((tap/3)*10 + (tap%3)) * 144u;
        const uint32_t wS = (uint32_t)tap * 9216u;
        #pragma unroll
        for (int k = 0; k < 4; k++) {
            const uint32_t ko = (uint32_t)k * 32u;
            uint32_t ah[4], al[4];
            ldsm_x4(ah, aBase + aS + ko);
            ldsm_x4(al, aBase + C2_ALO_D + aS + ko);
            #pragma unroll
            for (int nb = 0; nb < 4; nb++) {
                uint32_t bh[4], bl[4];
                const uint32_t bbadr = bBase[nb] + wS + ko;
                ldsm_x4(bh, bbadr);
                ldsm_x4(bl, bbadr + C2_WLO_D);
                mma_bf16(acc[2*nb],   ah, bh[0], bh[1]);   // hi*hi
                mma_bf16(acc[2*nb+1], ah, bh[2], bh[3]);
                mma_bf16(acc[2*nb],   ah, bl[0], bl[1]);   // hi*lo
                mma_bf16(acc[2*nb+1], ah, bl[2], bl[3]);
                mma_bf16(acc[2*nb],   al, bh[0], bh[1]);   // lo*hi
                mma_bf16(acc[2*nb+1], al, bh[2], bh[3]);
            }
        }
    }
    __syncthreads();   // all warps done reading A before overlaying D

    // 4) stage D[p][oc] fp32 into smem (documented m16n8 D layout)
    float* s_d = (float*)(smem + C2_AHI);    // 128*64*4 = 32 KB, overlays dead A
    #pragma unroll
    for (int nf = 0; nf < 8; nf++) {
        int oc = nf*8 + 2*(lane & 3);
        int p0 = wid*16 + (lane >> 2);
        s_d[p0*64 + oc]       = acc[nf][0];
        s_d[p0*64 + oc + 1]   = acc[nf][1];
        s_d[(p0+8)*64 + oc]     = acc[nf][2];
        s_d[(p0+8)*64 + oc + 1] = acc[nf][3];
    }
    __syncthreads();

    // 5) scalar pooling: thread -> pooled pixel q = tid/8, oc block (tid%8)*8
    {
        int q  = tid >> 3;                  // 0..31
        int oc0 = (tid & 7) * 8;
        int qy = q >> 2, qx = q & 3;
        int p00 = (qy*2)*8 + qx*2;          // conv pixel (2qy, 2qx)
        int oy = (cy0 >> 1) + qy, ox = (cx0 >> 1) + qx;
        #pragma unroll
        for (int j = 0; j < 8; j++) {
            int oc = oc0 + j;
            float m = fmaxf(fmaxf(s_d[p00*64 + oc],     s_d[(p00+1)*64 + oc]),
                            fmaxf(s_d[(p00+8)*64 + oc], s_d[(p00+9)*64 + oc]));
            g_h2[(((unsigned)(b*64 + oc))*56u + oy)*56u + ox] = leaky(m + s_bias[oc]);
        }
    }
}

// ---------------------------------------------------------------------------
// Kernel 3: FC split-K partials (proven)
// ---------------------------------------------------------------------------
__global__ __launch_bounds__(256) void fc_partial_kernel(const float* __restrict__ wfc)
{
    __shared__ __align__(16) float s_wt[10][1024];
    const int tid = threadIdx.x;
    const int k0  = blockIdx.x * 1024;

    for (int i = tid; i < 10240; i += 256) {
        int k = i / 10, c = i % 10;
        s_wt[c][k] = wfc[k0*10 + i];
    }
    __syncthreads();

    const int warp = tid >> 5, lane = tid & 31;
    for (int bg = 0; bg < 4; bg++) {
        int b = bg*8 + warp;
        float acc[10];
        #pragma unroll
        for (int c = 0; c < 10; c++) acc[c] = 0.f;

        const float4* hb = (const float4*)&g_h2[b*200704 + k0];
        for (int k4 = lane; k4 < 256; k4 += 32) {
            float4 hv = hb[k4];
            #pragma unroll
            for (int c = 0; c < 10; c++) {
                float4 wv = *(const float4*)&s_wt[c][k4*4];
                acc[c] += hv.x*wv.x + hv.y*wv.y + hv.z*wv.z + hv.w*wv.w;
            }
        }
        #pragma unroll
        for (int c = 0; c < 10; c++) {
            #pragma unroll
            for (int off = 16; off; off >>= 1)
                acc[c] += __shfl_xor_sync(0xffffffffu, acc[c], off);
        }
        if (lane == 0) {
            #pragma unroll
            for (int c = 0; c < 10; c++)
                g_fcp[(blockIdx.x*32 + b)*10 + c] = acc[c];
        }
    }
}

// ---------------------------------------------------------------------------
// Kernel 4: final deterministic reduction (proven)
// ---------------------------------------------------------------------------
__global__ __launch_bounds__(224) void fc_reduce_kernel(const float* __restrict__ bfc,
                                                        float* __restrict__ out)
{
    __shared__ float s_part[7][10];
    const int tid = threadIdx.x;
    const int b   = blockIdx.x;
    const int warp = tid >> 5, lane = tid & 31;

    float a[10];
    #pragma unroll
    for (int c = 0; c < 10; c++) a[c] = 0.f;

    if (tid < 196) {
        const float2* p = (const float2*)&g_fcp[(tid*32 + b)*10];
        #pragma unroll
        for (int h = 0; h < 5; h++) {
            float2 v = p[h];
            a[2*h]   = v.x;
            a[2*h+1] = v.y;
        }
    }
    #pragma unroll
    for (int c = 0; c < 10; c++) {
        #pragma unroll
        for (int off = 16; off; off >>= 1)
            a[c] += __shfl_xor_sync(0xffffffffu, a[c], off);
    }
    if (lane == 0)
        #pragma unroll
        for (int c = 0; c < 10; c++) s_part[warp][c] = a[c];
    __syncthreads();

    if (tid < 10) {
        float s = bfc[tid];
        #pragma unroll
        for (int w = 0; w < 7; w++) s += s_part[w][tid];
        out[b*10 + tid] = s;
    }
}

// ---------------------------------------------------------------------------
extern "C" void kernel_launch(void* const* d_in, const int* in_sizes, int n_in,
                              void* d_out, int out_size)
{
    const float* x   = (const float*)d_in[0];
    const float* w1  = (const float*)d_in[1];
    const float* b1  = (const float*)d_in[2];
    const float* w2  = (const float*)d_in[3];
    const float* b2  = (const float*)d_in[4];
    const float* wfc = (const float*)d_in[5];
    const float* bfc = (const float*)d_in[6];
    float* out = (float*)d_out;

    cudaFuncSetAttribute(conv2_kernel, cudaFuncAttributeMaxDynamicSharedMemorySize,
                         C2_TOTAL);

    prep_w2_kernel<<<36, 1024>>>(w2);
    conv1_kernel<<<dim3(49, 32), 256>>>(x, w1, b1);
    conv2_kernel<<<dim3(98, 32), 256, C2_TOTAL>>>(b2);
    fc_partial_kernel<<<196, 256>>>(wfc);
    fc_reduce_kernel<<<32, 224>>>(bfc, out);
}